// round 4
// baseline (speedup 1.0000x reference)
#include <cuda_runtime.h>
#include <cstdint>

// ----------------------------------------------------------------------------
// BaseLUTLayer = multilinear polynomial eval in coefficient (Moebius) basis.
//   prep_kernel:  (a) transpose x -> xT[IN][B]  (64x64 float4 tiles)
//                 (b) Moebius transform lut -> C (multilinear coefficients)
//   lut_fold_kernel: nested Horner, f32x2 packed over batch, BPT=8:
//     each thread evaluates 4 f32x2 batch-pairs against one output's 64
//     coefficients; each smem coefficient read (LDS.128, warp-broadcast) is
//     reused by all 4 sets -> kernel is fma-pipe bound (63 fma2 per b-pair).
// ----------------------------------------------------------------------------

#define O_TILE 8
#define BPT    8
#define B_TILE (32 * BPT)   // 256

__device__ float g_xT[4 * 1024 * 1024];
__device__ float g_C [1 * 1024 * 1024];

static __device__ __forceinline__ unsigned long long pack2(float lo, float hi) {
    unsigned long long r;
    asm("mov.b64 %0, {%1, %2};" : "=l"(r) : "f"(lo), "f"(hi));
    return r;
}
static __device__ __forceinline__ void unpack2(unsigned long long v, float& lo, float& hi) {
    asm("mov.b64 {%0, %1}, %2;" : "=f"(lo), "=f"(hi) : "l"(v));
}
static __device__ __forceinline__ unsigned long long fma2(unsigned long long a,
                                                          unsigned long long b,
                                                          unsigned long long c) {
    unsigned long long d;
    asm("fma.rn.f32x2 %0, %1, %2, %3;" : "=l"(d) : "l"(a), "l"(b), "l"(c));
    return d;
}

// ---- fused prep: transpose (first t_blocks) + Moebius coeffs (rest) --------
__global__ __launch_bounds__(256)
void prep_kernel(const float* __restrict__ x, float* __restrict__ xT,
                 const float* __restrict__ lut, float* __restrict__ C,
                 int B, int IN, int OUT, int t_blocks, int tiles_x) {
    if ((int)blockIdx.x < t_blocks) {
        // -------- 64x64 transpose tile, float4 I/O --------
        __shared__ float tile[64][65];
        const int tid = threadIdx.x;
        const int c0 = (blockIdx.x % tiles_x) * 64;   // IN base
        const int r0 = (blockIdx.x / tiles_x) * 64;   // B base
#pragma unroll
        for (int p = 0; p < 4; p++) {
            int idx  = p * 256 + tid;
            int row  = idx >> 4;            // 0..63 (B-local)
            int col4 = idx & 15;            // 0..15
            int r = r0 + row, c = c0 + col4 * 4;
            if (r < B && c + 3 < IN) {
                float4 v = __ldg(reinterpret_cast<const float4*>(&x[(size_t)r * IN + c]));
                tile[row][col4 * 4 + 0] = v.x;
                tile[row][col4 * 4 + 1] = v.y;
                tile[row][col4 * 4 + 2] = v.z;
                tile[row][col4 * 4 + 3] = v.w;
            }
        }
        __syncthreads();
#pragma unroll
        for (int p = 0; p < 4; p++) {
            int idx = p * 256 + tid;
            int inl = idx >> 4;             // 0..63 (IN-local)
            int b4  = idx & 15;
            int in = c0 + inl, bb = r0 + b4 * 4;
            if (in < IN && bb + 3 < B) {
                float4 v = make_float4(tile[b4 * 4 + 0][inl],
                                       tile[b4 * 4 + 1][inl],
                                       tile[b4 * 4 + 2][inl],
                                       tile[b4 * 4 + 3][inl]);
                *reinterpret_cast<float4*>(&xT[(size_t)in * B + bb]) = v;
            }
        }
    } else {
        // -------- Moebius transform: one thread per output row --------
        int o = (blockIdx.x - t_blocks) * 256 + threadIdx.x;
        if (o >= OUT) return;
        float a[64];
        const float4* src = reinterpret_cast<const float4*>(lut + (size_t)o * 64);
#pragma unroll
        for (int i = 0; i < 16; i++) {
            float4 v = __ldg(&src[i]);
            a[4 * i] = v.x; a[4 * i + 1] = v.y; a[4 * i + 2] = v.z; a[4 * i + 3] = v.w;
        }
#pragma unroll
        for (int j = 0; j < 6; j++) {
            int s = 1 << j;
#pragma unroll
            for (int k = 0; k < 64; k++)
                if (k & s) a[k] -= a[k ^ s];
        }
        float4* dst = reinterpret_cast<float4*>(C + (size_t)o * 64);
#pragma unroll
        for (int i = 0; i < 16; i++)
            dst[i] = make_float4(a[4 * i], a[4 * i + 1], a[4 * i + 2], a[4 * i + 3]);
    }
}

// ---- fold: 4 f32x2 sets per thread, coefficient reuse across sets ----------
__global__ __launch_bounds__(32 * O_TILE, 2)
void lut_fold_kernel(const float* __restrict__ xT,
                     const float* __restrict__ C,
                     const int*   __restrict__ mapping,
                     float* __restrict__ out,
                     int B, int OUT) {
    __shared__ ulonglong2 s_lut[O_TILE][32];          // {dup c_even, dup c_odd}
    __shared__ int        s_map[O_TILE][6];
    __shared__ float      s_res[O_TILE][B_TILE + 4];  // row stride 260 = 65*16B

    const int lane = threadIdx.x;
    const int ty   = threadIdx.y;
    const int tid  = ty * 32 + lane;
    const int b0   = blockIdx.x * B_TILE;
    const int o0   = blockIdx.y * O_TILE;

    {
        int oo = tid >> 5, k = tid & 31;
        int o  = o0 + oo;
        float2 c = make_float2(0.f, 0.f);
        if (o < OUT) c = *reinterpret_cast<const float2*>(&C[(size_t)o * 64 + 2 * k]);
        ulonglong2 e;
        e.x = pack2(c.x, c.x);
        e.y = pack2(c.y, c.y);
        s_lut[oo][k] = e;
    }
    if (tid < O_TILE * 6) {
        int oo = tid / 6, j = tid % 6;
        int o = o0 + oo;
        s_map[oo][j] = (o < OUT) ? mapping[(size_t)o * 6 + j] : 0;
    }
    __syncthreads();

    const int bq = b0 + lane * BPT;                   // 8 consecutive b
    const bool vb = (bq + BPT - 1 < B);

    // packed x: 4 f32x2 sets per bit, two LDG.128 each
    unsigned long long X[4][6];
#pragma unroll
    for (int j = 0; j < 6; j++) {
        if (vb) {
            const float* p = &xT[(size_t)s_map[ty][j] * B + bq];
            ulonglong2 lo = *reinterpret_cast<const ulonglong2*>(p);
            ulonglong2 hi = *reinterpret_cast<const ulonglong2*>(p + 4);
            X[0][j] = lo.x; X[1][j] = lo.y; X[2][j] = hi.x; X[3][j] = hi.y;
        } else {
#pragma unroll
            for (int s = 0; s < 4; s++) X[s][j] = 0ull;
        }
    }

    const ulonglong2* lrow = &s_lut[ty][0];

    unsigned long long acc[4], acc2[4];
#pragma unroll
    for (int g = 0; g < 4; g++) {
        ulonglong2 e[8];
#pragma unroll
        for (int i = 0; i < 8; i++) e[i] = lrow[g * 8 + i];   // LDS.128 bcast
#pragma unroll
        for (int s = 0; s < 4; s++) {
            unsigned long long v[8];
#pragma unroll
            for (int i = 0; i < 8; i++)                        // bit 0
                v[i] = fma2(X[s][0], e[i].y, e[i].x);
#pragma unroll
            for (int i = 0; i < 4; i++)                        // bit 1
                v[i] = fma2(X[s][1], v[2 * i + 1], v[2 * i]);
#pragma unroll
            for (int i = 0; i < 2; i++)                        // bit 2
                v[i] = fma2(X[s][2], v[2 * i + 1], v[2 * i]);
            unsigned long long rg = fma2(X[s][3], v[1], v[0]); // bit 3
            if (g == 0)      acc[s]  = rg;
            else if (g == 1) acc[s]  = fma2(X[s][4], rg, acc[s]);    // bit 4
            else if (g == 2) acc2[s] = rg;
            else             acc2[s] = fma2(X[s][4], rg, acc2[s]);
        }
    }

    // bit 5 + stage results
#pragma unroll
    for (int s = 0; s < 4; s += 2) {
        unsigned long long r0 = fma2(X[s][5],     acc2[s],     acc[s]);
        unsigned long long r1 = fma2(X[s + 1][5], acc2[s + 1], acc[s + 1]);
        float a0, a1, b0f, b1f;
        unpack2(r0, a0, a1);
        unpack2(r1, b0f, b1f);
        *reinterpret_cast<float4*>(&s_res[ty][lane * BPT + 2 * s]) =
            make_float4(a0, a1, b0f, b1f);
    }
    __syncthreads();

    // writeout: o fastest, float4 stores, full 32B sectors
#pragma unroll
    for (int it = 0; it < 2; it++) {
        int idx  = it * 256 + tid;
        int half = idx & 1;
        int bw   = idx >> 1;
        int o    = o0 + half * 4;
        int bg   = b0 + bw;
        if (bg < B && o + 3 < OUT) {
            float4 val = make_float4(s_res[half * 4 + 0][bw],
                                     s_res[half * 4 + 1][bw],
                                     s_res[half * 4 + 2][bw],
                                     s_res[half * 4 + 3][bw]);
            *reinterpret_cast<float4*>(&out[(size_t)bg * OUT + o]) = val;
        }
    }
}

extern "C" void kernel_launch(void* const* d_in, const int* in_sizes, int n_in,
                              void* d_out, int out_size) {
    const float* x       = (const float*)d_in[0];
    const float* lut     = (const float*)d_in[1];
    const int*   mapping = (const int*)d_in[2];
    float*       out     = (float*)d_out;

    int OUT = in_sizes[2] / 6;          // mapping is (OUT, 6)
    int B   = out_size / OUT;           // out is (B, OUT)
    int IN  = in_sizes[0] / B;          // x is (B, IN)

    float* xT = nullptr;
    float* C  = nullptr;
    cudaGetSymbolAddress((void**)&xT, g_xT);
    cudaGetSymbolAddress((void**)&C,  g_C);

    int tiles_x  = (IN + 63) / 64;
    int tiles_y  = (B + 63) / 64;
    int t_blocks = tiles_x * tiles_y;
    int c_blocks = (OUT + 255) / 256;
    prep_kernel<<<t_blocks + c_blocks, 256>>>(x, xT, lut, C, B, IN, OUT, t_blocks, tiles_x);

    dim3 blk(32, O_TILE);
    dim3 grd((B + B_TILE - 1) / B_TILE, (OUT + O_TILE - 1) / O_TILE);
    lut_fold_kernel<<<grd, blk>>>(xT, C, mapping, out, B, OUT);
}

// round 5
// speedup vs baseline: 1.1098x; 1.1098x over previous
#include <cuda_runtime.h>
#include <cstdint>

// ----------------------------------------------------------------------------
// BaseLUTLayer = multilinear polynomial eval in Moebius coefficient basis.
//   prep_kernel:  (a) transpose x -> xT[IN][B], 128x64 regions (8 LDG.128/phase)
//                 (b) Moebius transform lut -> C
//   lut_fold_kernel: nested Horner, f32x2 over batch, BPT=4 (regs~40, occ~66%).
//     Warps are self-sufficient at entry: per-warp mapping load -> immediate
//     x LDGs -> per-warp coefficient smem fill (+syncwarp only). The only
//     block barrier is before the transposed sector-friendly writeout.
// ----------------------------------------------------------------------------

#define O_TILE 8
#define BPT    4
#define B_TILE (32 * BPT)   // 128

__device__ float g_xT[4 * 1024 * 1024];
__device__ float g_C [1 * 1024 * 1024];

static __device__ __forceinline__ unsigned long long pack2(float lo, float hi) {
    unsigned long long r;
    asm("mov.b64 %0, {%1, %2};" : "=l"(r) : "f"(lo), "f"(hi));
    return r;
}
static __device__ __forceinline__ void unpack2(unsigned long long v, float& lo, float& hi) {
    asm("mov.b64 {%0, %1}, %2;" : "=f"(lo), "=f"(hi) : "l"(v));
}
static __device__ __forceinline__ unsigned long long fma2(unsigned long long a,
                                                          unsigned long long b,
                                                          unsigned long long c) {
    unsigned long long d;
    asm("fma.rn.f32x2 %0, %1, %2, %3;" : "=l"(d) : "l"(a), "l"(b), "l"(c));
    return d;
}

// ---- fused prep: transpose (first t_blocks) + Moebius coeffs (rest) --------
__global__ __launch_bounds__(256)
void prep_kernel(const float* __restrict__ x, float* __restrict__ xT,
                 const float* __restrict__ lut, float* __restrict__ C,
                 int B, int IN, int OUT, int t_blocks, int tiles_x) {
    if ((int)blockIdx.x < t_blocks) {
        // -------- 128x64 transpose region (B x IN), deep load pipeline ------
        __shared__ float tile[128][65];
        const int tid = threadIdx.x;
        const int c0 = (blockIdx.x % tiles_x) * 64;    // IN base
        const int r0 = (blockIdx.x / tiles_x) * 128;   // B base

        float4 v[8];
#pragma unroll
        for (int p = 0; p < 8; p++) {                  // 8 LDG.128 in flight
            int idx  = p * 256 + tid;
            int row  = idx >> 4;                       // 0..127 (B-local)
            int col4 = idx & 15;
            int r = r0 + row, c = c0 + col4 * 4;
            v[p] = (r < B && c + 3 < IN)
                 ? __ldg(reinterpret_cast<const float4*>(&x[(size_t)r * IN + c]))
                 : make_float4(0.f, 0.f, 0.f, 0.f);
        }
#pragma unroll
        for (int p = 0; p < 8; p++) {
            int idx  = p * 256 + tid;
            int row  = idx >> 4;
            int col4 = idx & 15;
            tile[row][col4 * 4 + 0] = v[p].x;
            tile[row][col4 * 4 + 1] = v[p].y;
            tile[row][col4 * 4 + 2] = v[p].z;
            tile[row][col4 * 4 + 3] = v[p].w;
        }
        __syncthreads();
#pragma unroll
        for (int p = 0; p < 8; p++) {
            int idx = p * 256 + tid;
            int inl = idx >> 5;                        // 0..63 (IN-local)
            int b4  = idx & 31;                        // 0..31
            int in = c0 + inl, bb = r0 + b4 * 4;
            if (in < IN && bb + 3 < B) {
                float4 w = make_float4(tile[b4 * 4 + 0][inl],
                                       tile[b4 * 4 + 1][inl],
                                       tile[b4 * 4 + 2][inl],
                                       tile[b4 * 4 + 3][inl]);
                *reinterpret_cast<float4*>(&xT[(size_t)in * B + bb]) = w;
            }
        }
    } else {
        // -------- Moebius transform: one thread per output row --------------
        int o = (blockIdx.x - t_blocks) * 256 + threadIdx.x;
        if (o >= OUT) return;
        float a[64];
        const float4* src = reinterpret_cast<const float4*>(lut + (size_t)o * 64);
#pragma unroll
        for (int i = 0; i < 16; i++) {
            float4 w = __ldg(&src[i]);
            a[4 * i] = w.x; a[4 * i + 1] = w.y; a[4 * i + 2] = w.z; a[4 * i + 3] = w.w;
        }
#pragma unroll
        for (int j = 0; j < 6; j++) {
            int s = 1 << j;
#pragma unroll
            for (int k = 0; k < 64; k++)
                if (k & s) a[k] -= a[k ^ s];
        }
        float4* dst = reinterpret_cast<float4*>(C + (size_t)o * 64);
#pragma unroll
        for (int i = 0; i < 16; i++)
            dst[i] = make_float4(a[4 * i], a[4 * i + 1], a[4 * i + 2], a[4 * i + 3]);
    }
}

// ---- fold: warp-autonomous start, BPT=4, only one block barrier ------------
__global__ __launch_bounds__(32 * O_TILE)
void lut_fold_kernel(const float* __restrict__ xT,
                     const float* __restrict__ C,
                     const int*   __restrict__ mapping,
                     float* __restrict__ out,
                     int B, int OUT) {
    __shared__ ulonglong2 s_lut[O_TILE][32];
    __shared__ float      s_res[O_TILE][B_TILE + 4];

    const int lane = threadIdx.x;
    const int ty   = threadIdx.y;
    const int tid  = ty * 32 + lane;
    const int b0   = blockIdx.x * B_TILE;
    const int o0   = blockIdx.y * O_TILE;
    int o = o0 + ty;
    if (o >= OUT) o = OUT - 1;

    // per-warp coefficient pair (independent of mapping -> issue first)
    float2 cpair = *reinterpret_cast<const float2*>(&C[(size_t)o * 64 + 2 * lane]);

    // per-warp mapping row (uniform across lanes; L1-hot after first block)
    int m[6];
#pragma unroll
    for (int j = 0; j < 6; j++) m[j] = __ldg(&mapping[(size_t)o * 6 + j]);

    // x loads: one LDG.128 per bit = both f32x2 sets, issued ASAP
    const int bq = b0 + lane * BPT;
    const bool vb = (bq + BPT - 1 < B);
    unsigned long long Xa[6], Xb[6];
#pragma unroll
    for (int j = 0; j < 6; j++) {
        if (vb) {
            ulonglong2 xv = *reinterpret_cast<const ulonglong2*>(&xT[(size_t)m[j] * B + bq]);
            Xa[j] = xv.x;
            Xb[j] = xv.y;
        } else {
            Xa[j] = 0ull; Xb[j] = 0ull;
        }
    }

    // per-warp smem coefficient row: lane k owns pair (2k, 2k+1)
    {
        ulonglong2 e;
        e.x = pack2(cpair.x, cpair.x);
        e.y = pack2(cpair.y, cpair.y);
        s_lut[ty][lane] = e;
    }
    __syncwarp();

    const ulonglong2* lrow = &s_lut[ty][0];

    unsigned long long ra[4], rb[4];
#pragma unroll
    for (int g = 0; g < 4; g++) {
        unsigned long long va[8], vbv[8];
#pragma unroll
        for (int i = 0; i < 8; i++) {
            ulonglong2 e = lrow[g * 8 + i];            // LDS.128 warp-broadcast
            va[i]  = fma2(Xa[0], e.y, e.x);            // bit 0
            vbv[i] = fma2(Xb[0], e.y, e.x);
        }
#pragma unroll
        for (int i = 0; i < 4; i++) {                  // bit 1
            va[i]  = fma2(Xa[1], va[2 * i + 1],  va[2 * i]);
            vbv[i] = fma2(Xb[1], vbv[2 * i + 1], vbv[2 * i]);
        }
#pragma unroll
        for (int i = 0; i < 2; i++) {                  // bit 2
            va[i]  = fma2(Xa[2], va[2 * i + 1],  va[2 * i]);
            vbv[i] = fma2(Xb[2], vbv[2 * i + 1], vbv[2 * i]);
        }
        ra[g] = fma2(Xa[3], va[1],  va[0]);            // bit 3
        rb[g] = fma2(Xb[3], vbv[1], vbv[0]);
    }
    unsigned long long sa0 = fma2(Xa[4], ra[1], ra[0]);    // bit 4
    unsigned long long sa1 = fma2(Xa[4], ra[3], ra[2]);
    unsigned long long sb0 = fma2(Xb[4], rb[1], rb[0]);
    unsigned long long sb1 = fma2(Xb[4], rb[3], rb[2]);
    unsigned long long resa = fma2(Xa[5], sa1, sa0);       // bit 5
    unsigned long long resb = fma2(Xb[5], sb1, sb0);

    float r0f, r1f, r2f, r3f;
    unpack2(resa, r0f, r1f);
    unpack2(resb, r2f, r3f);
    *reinterpret_cast<float4*>(&s_res[ty][lane * BPT]) = make_float4(r0f, r1f, r2f, r3f);
    __syncthreads();

    // writeout: o fastest, float4 stores (full 32B sectors)
    int bw   = tid >> 1;          // 0..127
    int half = tid & 1;
    int oo   = o0 + half * 4;
    int bg   = b0 + bw;
    if (bg < B && oo + 3 < OUT) {
        float4 val = make_float4(s_res[half * 4 + 0][bw],
                                 s_res[half * 4 + 1][bw],
                                 s_res[half * 4 + 2][bw],
                                 s_res[half * 4 + 3][bw]);
        *reinterpret_cast<float4*>(&out[(size_t)bg * OUT + oo]) = val;
    }
}

extern "C" void kernel_launch(void* const* d_in, const int* in_sizes, int n_in,
                              void* d_out, int out_size) {
    const float* x       = (const float*)d_in[0];
    const float* lut     = (const float*)d_in[1];
    const int*   mapping = (const int*)d_in[2];
    float*       out     = (float*)d_out;

    int OUT = in_sizes[2] / 6;          // mapping is (OUT, 6)
    int B   = out_size / OUT;           // out is (B, OUT)
    int IN  = in_sizes[0] / B;          // x is (B, IN)

    float* xT = nullptr;
    float* C  = nullptr;
    cudaGetSymbolAddress((void**)&xT, g_xT);
    cudaGetSymbolAddress((void**)&C,  g_C);

    int tiles_x  = (IN + 63) / 64;
    int tiles_y  = (B + 127) / 128;
    int t_blocks = tiles_x * tiles_y;
    int c_blocks = (OUT + 255) / 256;
    prep_kernel<<<t_blocks + c_blocks, 256>>>(x, xT, lut, C, B, IN, OUT, t_blocks, tiles_x);

    dim3 blk(32, O_TILE);
    dim3 grd((B + B_TILE - 1) / B_TILE, (OUT + O_TILE - 1) / O_TILE);
    lut_fold_kernel<<<grd, blk>>>(xT, C, mapping, out, B, OUT);
}